// round 8
// baseline (speedup 1.0000x reference)
#include <cuda_runtime.h>
#include <cuda_bf16.h>
#include <cstdint>

// Problem constants
#define KC   1024
#define DD   64
#define BB   32
#define TT   2048
#define NV   (BB*TT)
#define QE   (BB*DD*TT)
#define DECAYF 0.99f
#define OMD    (1.0f - 0.99f)
#define COMMITF 0.25f
#define EPSF 1e-5f
#define NCAND 6

// int8 quantization scales
#define SZQ   (127.0f/6.0f)      // z scale
#define SEQ   (127.0f/5.0f)      // embedding scale
#define SPROD ((6.0f/127.0f)*(5.0f/127.0f))

// Output layout (flat float32, reference tuple order)
#define OFF_Q      0
#define OFF_LOSS   (OFF_Q + QE)
#define OFF_CODES  (OFF_LOSS + 1)
#define OFF_NEWEMB (OFF_CODES + NV)
#define OFF_NEWCS  (OFF_NEWEMB + KC*DD)
#define OFF_NEWW   (OFF_NEWCS + KC)

// Scratch (device globals — no allocation)
__device__ float g_hn[KC];
__device__ int   g_hni[KC];
__device__ float g_counts[KC];
__device__ float g_dw[KC*DD];
__device__ float g_loss;
__device__ __align__(256) char g_eq[KC*DD];   // int8 quantized embedding

#define SWZ(o) ((o) ^ (((o) >> 3) & 0x70))

__device__ __forceinline__ uint32_t smem_u32(const void* p) {
    uint32_t a;
    asm("{ .reg .u64 t; cvta.to.shared.u64 t, %1; cvt.u32.u64 %0, t; }" : "=r"(a) : "l"(p));
    return a;
}

#define MMA_S8(acc, A, B0, B1)                                                 \
    asm volatile("mma.sync.aligned.m16n8k32.row.col.s32.s8.s8.s32 "            \
        "{%0,%1,%2,%3},{%4,%5,%6,%7},{%8,%9},{%0,%1,%2,%3};"                   \
        : "+r"((acc)[0]), "+r"((acc)[1]), "+r"((acc)[2]), "+r"((acc)[3])       \
        : "r"((A)[0]), "r"((A)[1]), "r"((A)[2]), "r"((A)[3]),                  \
          "r"(B0), "r"(B1))

#define CP_ASYNC16(dst_u32, src_ptr)                                           \
    asm volatile("cp.async.cg.shared.global [%0], [%1], 16;"                   \
                 :: "r"(dst_u32), "l"(src_ptr) : "memory")
#define CP_COMMIT() asm volatile("cp.async.commit_group;" ::: "memory")
#define CP_WAIT1()  asm volatile("cp.async.wait_group 1;" ::: "memory")
#define CP_WAIT0()  asm volatile("cp.async.wait_group 0;" ::: "memory")

// SMEM layout: A-int8 16KB | B double buffer 2x16KB | hni 4KB
#define SM_AH    0
#define SM_B     16384
#define SM_HN    49152
#define SM_CAND  SM_AH                  // reused after MMA loop
#define SM_TOTAL (SM_HN + 4096 + 128)

// ---------------------------------------------------------------------------
// Prep: zero scratch, half-norms (+int), int8 quantized embedding
// ---------------------------------------------------------------------------
__global__ void vq_prep(const float* __restrict__ emb) {
    int i = blockIdx.x * 256 + threadIdx.x;   // 65536 threads
    g_dw[i] = 0.0f;
    {
        int q = __float2int_rn(emb[i] * SEQ);
        q = max(-127, min(127, q));
        g_eq[i] = (char)q;
    }
    if (i < KC) {
        g_counts[i] = 0.0f;
        const float4* r = (const float4*)(emb + (size_t)i * DD);
        float s = 0.0f;
        #pragma unroll
        for (int j = 0; j < 16; ++j) {
            float4 v = r[j];
            s += v.x * v.x + v.y * v.y + v.z * v.z + v.w * v.w;
        }
        g_hn[i]  = 0.5f * s;
        g_hni[i] = __float2int_rn(0.5f * s / SPROD);
    }
    if (i == 0) g_loss = 0.0f;
}

// ---------------------------------------------------------------------------
// Main: IMMA int8 screen (integer score in accumulator) + lane top-4 + rescore
// ---------------------------------------------------------------------------
extern __shared__ __align__(1024) char smc[];

// Merge 2 new values into sorted ascending top-4 (v0<=..<=v3). 12 int min/max.
__device__ __forceinline__ void ins4p(int v[4], int a, int b) {
    int a0 = min(a, b), a1 = max(a, b);
    int t0 = max(v[0], a0);
    v[0]   = min(v[0], a0);
    int t1 = min(v[1], a1);
    int w  = max(v[1], a1);
    int r1 = min(t0, t1);
    int u  = max(t0, t1);
    int r2 = min(v[2], u);
    int r3 = min(min(v[3], max(v[2], u)), w);
    v[1] = r1; v[2] = r2; v[3] = r3;
}
__device__ __forceinline__ void ins6(int v[6], int t) {
    #pragma unroll
    for (int i = 0; i < 6; ++i) {
        int lo = min(t, v[i]);
        t = max(t, v[i]);
        v[i] = lo;
    }
}

__device__ __forceinline__ void load_bchunk_async(uint32_t sb, int c, int buf, int tid) {
    #pragma unroll
    for (int i = 0; i < 4; ++i) {
        int idx  = tid + i * 128;            // 0..511
        int code = idx >> 2;
        int ch   = idx & 3;
        const char* src = g_eq + (size_t)(c * 128 + code) * DD + ch * 16;
        uint32_t doff = SM_B + buf * 16384 + SWZ((uint32_t)(code * 128 + ch * 16));
        CP_ASYNC16(sb + doff, src);
    }
}

__global__ __launch_bounds__(128, 4) void vq_main_mma(
        const float* __restrict__ z,
        const float* __restrict__ emb,
        float* __restrict__ out) {
    __shared__ float swr[4];
    const int tid  = threadIdx.x;
    const int wid  = tid >> 5;
    const int lane = tid & 31;
    const uint32_t sb = smem_u32(smc);

    const int n = blockIdx.x * 128 + tid;
    const int b = n >> 11;
    const int t = n & 2047;
    const float* zp = z + (size_t)b * (DD * TT) + t;

    // --- Stage A: load z (coalesced), quantize NEGATED int8, swizzled store
    #pragma unroll
    for (int d = 0; d < DD; d += 4) {
        int q[4];
        #pragma unroll
        for (int j = 0; j < 4; ++j) {
            int v = __float2int_rn(-zp[(size_t)(d + j) * TT] * SZQ);
            q[j] = max(-127, min(127, v));
        }
        uint32_t w = (uint32_t)(q[0] & 255) | ((uint32_t)(q[1] & 255) << 8)
                   | ((uint32_t)(q[2] & 255) << 16) | ((uint32_t)q[3] << 24);
        *(uint32_t*)(smc + SM_AH + SWZ((uint32_t)(tid * 128 + d))) = w;
    }
    int* shn = (int*)(smc + SM_HN);
    #pragma unroll
    for (int i = 0; i < 8; ++i) shn[tid + i * 128] = g_hni[tid + i * 128];

    // Prefetch B chunks 0, 1
    load_bchunk_async(sb, 0, 0, tid); CP_COMMIT();
    load_bchunk_async(sb, 1, 1, tid); CP_COMMIT();

    __syncthreads();

    // --- A fragments: 2 m-tiles x 2 k-halves x 4 regs (hold -qx)
    uint32_t ah[2][2][4];
    #pragma unroll
    for (int mt = 0; mt < 2; ++mt) {
        int base_r = wid * 32 + mt * 16 + (lane >> 2);
        #pragma unroll
        for (int kh = 0; kh < 2; ++kh) {
            #pragma unroll
            for (int q = 0; q < 4; ++q) {
                int row = base_r + (q & 1) * 8;
                uint32_t off = SWZ((uint32_t)(row * 128 + kh * 32
                                  + (lane & 3) * 4 + (q >> 1) * 16));
                ah[mt][kh][q] = *(const uint32_t*)(smc + SM_AH + off);
            }
        }
    }

    // Per-slot sorted top-4 trackers (int packed score|idx)
    int tv[4][4];
    #pragma unroll
    for (int s = 0; s < 4; ++s)
        #pragma unroll
        for (int j = 0; j < 4; ++j) tv[s][j] = 0x7FFFFFFF;

    // --- Chunk loop: 8 chunks x 128 codes
    for (int c = 0; c < 8; ++c) {
        if (c < 7) CP_WAIT1(); else CP_WAIT0();
        __syncthreads();
        const char* bb = smc + SM_B + (c & 1) * 16384;

        #pragma unroll 1
        for (int nt = 0; nt < 16; ++nt) {
            int brow = nt * 8 + (lane >> 2);
            uint32_t bw[2][2];
            #pragma unroll
            for (int kh = 0; kh < 2; ++kh) {
                uint32_t o0 = SWZ((uint32_t)(brow * 128 + kh * 32 + (lane & 3) * 4));
                uint32_t o1 = SWZ((uint32_t)(brow * 128 + kh * 32 + (lane & 3) * 4 + 16));
                bw[kh][0] = *(const uint32_t*)(bb + o0);
                bw[kh][1] = *(const uint32_t*)(bb + o1);
            }
            int c0 = c * 128 + nt * 8 + (lane & 3) * 2;
            int h0 = shn[c0], h1 = shn[c0 + 1];
            // acc init = h_int: score_int = h_int - qx.qe lands in acc
            int acc0[4] = {h0, h1, h0, h1};
            int acc1[4] = {h0, h1, h0, h1};
            MMA_S8(acc0, ah[0][0], bw[0][0], bw[0][1]);
            MMA_S8(acc0, ah[0][1], bw[1][0], bw[1][1]);
            MMA_S8(acc1, ah[1][0], bw[0][0], bw[0][1]);
            MMA_S8(acc1, ah[1][1], bw[1][0], bw[1][1]);
            ins4p(tv[0], acc0[0] * 1024 + c0, acc0[1] * 1024 + c0 + 1);
            ins4p(tv[1], acc0[2] * 1024 + c0, acc0[3] * 1024 + c0 + 1);
            ins4p(tv[2], acc1[0] * 1024 + c0, acc1[1] * 1024 + c0 + 1);
            ins4p(tv[3], acc1[2] * 1024 + c0, acc1[3] * 1024 + c0 + 1);
        }
        __syncthreads();
        if (c < 6) { load_bchunk_async(sb, c + 2, c & 1, tid); CP_COMMIT(); }
    }

    // --- Cross-lane butterfly merge (4 lanes, disjoint code sets) -> top-6
    int* ci = (int*)(smc + SM_CAND);
    #pragma unroll
    for (int s = 0; s < 4; ++s) {
        int m[6] = {tv[s][0], tv[s][1], tv[s][2], tv[s][3], 0x7FFFFFFF, 0x7FFFFFFF};
        #pragma unroll
        for (int off = 1; off <= 2; off <<= 1) {
            int p[6];
            #pragma unroll
            for (int j = 0; j < 6; ++j) p[j] = __shfl_xor_sync(0xffffffffu, m[j], off);
            #pragma unroll
            for (int j = 0; j < 6; ++j) ins6(m, p[j]);
        }
        if ((lane & 3) == 0) {
            int row = wid * 32 + (s >> 1) * 16 + (s & 1) * 8 + (lane >> 2);
            #pragma unroll
            for (int j = 0; j < NCAND; ++j)
                ci[row * NCAND + j] = m[j] & 1023;
        }
    }
    __syncthreads();

    // --- Load x into registers (coalesced), exact fp32 rescore of 6 cands
    float xr[DD];
    #pragma unroll
    for (int d = 0; d < DD; ++d) xr[d] = zp[(size_t)d * TT];

    float bestv = 3.4e38f;
    int   besti = 0;
    #pragma unroll
    for (int j = 0; j < NCAND; ++j) {
        int idx = ci[tid * NCAND + j];
        const float4* er = (const float4*)(emb + (size_t)idx * DD);
        float dot = 0.0f;
        #pragma unroll
        for (int q = 0; q < 16; ++q) {
            float4 e4 = __ldg(er + q);
            dot = fmaf(xr[4 * q + 0], e4.x, dot);
            dot = fmaf(xr[4 * q + 1], e4.y, dot);
            dot = fmaf(xr[4 * q + 2], e4.z, dot);
            dot = fmaf(xr[4 * q + 3], e4.w, dot);
        }
        float v = g_hn[idx] - dot;
        if (v < bestv || (v == bestv && idx < besti)) { bestv = v; besti = idx; }
    }

    // --- Epilogue: quantized write, loss, codes, segment sums
    const float4* er = (const float4*)(emb + (size_t)besti * DD);
    float* oq = out + OFF_Q + (size_t)b * (DD * TT) + t;
    float* dwp = g_dw + (size_t)besti * DD;
    float lsum = 0.0f;
    #pragma unroll
    for (int j = 0; j < 16; ++j) {
        float4 e4 = __ldg(er + j);
        float x0 = xr[4 * j + 0], x1 = xr[4 * j + 1];
        float x2 = xr[4 * j + 2], x3 = xr[4 * j + 3];
        oq[(size_t)(4 * j + 0) * TT] = e4.x;
        oq[(size_t)(4 * j + 1) * TT] = e4.y;
        oq[(size_t)(4 * j + 2) * TT] = e4.z;
        oq[(size_t)(4 * j + 3) * TT] = e4.w;
        float q0 = e4.x - x0, q1 = e4.y - x1, q2 = e4.z - x2, q3 = e4.w - x3;
        lsum += q0 * q0 + q1 * q1 + q2 * q2 + q3 * q3;
        asm volatile("red.global.add.v4.f32 [%0], {%1,%2,%3,%4};"
                     :: "l"(dwp + 4 * j), "f"(x0), "f"(x1), "f"(x2), "f"(x3) : "memory");
    }
    out[OFF_CODES + n] = (float)besti;
    atomicAdd(&g_counts[besti], 1.0f);

    #pragma unroll
    for (int o = 16; o; o >>= 1) lsum += __shfl_xor_sync(0xffffffffu, lsum, o);
    if (lane == 0) swr[wid] = lsum;
    __syncthreads();
    if (tid == 0)
        atomicAdd(&g_loss, swr[0] + swr[1] + swr[2] + swr[3]);
}

// ---------------------------------------------------------------------------
// Finalize (merged): nsum reduction per block, new_cs/loss (block 0),
// new_w + new_embedding everywhere.  256 blocks x 256 threads.
// ---------------------------------------------------------------------------
__global__ __launch_bounds__(256) void vq_fin(
        const float* __restrict__ ema_cs,
        const float* __restrict__ ema_w,
        float* __restrict__ out) {
    __shared__ float sw[8];
    __shared__ float snv;
    int tid = threadIdx.x;
    int i = blockIdx.x * 256 + tid;

    // Block-local full reduction of new_cs over all K codes
    float s = 0.0f;
    #pragma unroll
    for (int j = 0; j < 4; ++j) {
        int k = tid * 4 + j;
        s += DECAYF * ema_cs[k] + OMD * g_counts[k];
    }
    #pragma unroll
    for (int o = 16; o; o >>= 1) s += __shfl_xor_sync(0xffffffffu, s, o);
    if ((tid & 31) == 0) sw[tid >> 5] = s;
    __syncthreads();
    if (tid < 32) {
        float u = (tid < 8) ? sw[tid] : 0.0f;
        #pragma unroll
        for (int o = 4; o; o >>= 1) u += __shfl_xor_sync(0xffffffffu, u, o);
        if (tid == 0) snv = u;
    }
    __syncthreads();
    float nsum = snv;

    if (blockIdx.x == 0) {
        #pragma unroll
        for (int j = 0; j < 4; ++j) {
            int k = tid * 4 + j;
            out[OFF_NEWCS + k] = DECAYF * ema_cs[k] + OMD * g_counts[k];
        }
        if (tid == 0) out[OFF_LOSS] = COMMITF * g_loss * (1.0f / (float)QE);
    }

    int k = i >> 6;
    float cs = DECAYF * ema_cs[k] + OMD * g_counts[k];
    float cluster = (cs + EPSF) / (nsum + (float)KC * EPSF) * nsum;
    float nw = DECAYF * ema_w[i] + OMD * g_dw[i];
    out[OFF_NEWW + i] = nw;
    out[OFF_NEWEMB + i] = nw * (1.0f / cluster);
}

// ---------------------------------------------------------------------------
extern "C" void kernel_launch(void* const* d_in, const int* in_sizes, int n_in,
                              void* d_out, int out_size) {
    const float* z      = (const float*)d_in[0];
    const float* emb    = (const float*)d_in[1];
    const float* ema_cs = (const float*)d_in[2];
    const float* ema_w  = (const float*)d_in[3];
    float* out = (float*)d_out;

    cudaFuncSetAttribute(vq_main_mma, cudaFuncAttributeMaxDynamicSharedMemorySize, SM_TOTAL);

    vq_prep<<<256, 256>>>(emb);
    vq_main_mma<<<512, 128, SM_TOTAL>>>(z, emb, out);
    vq_fin<<<256, 256>>>(ema_cs, ema_w, out);
}

// round 9
// speedup vs baseline: 1.2102x; 1.2102x over previous
#include <cuda_runtime.h>
#include <cuda_fp16.h>
#include <cstdint>

// Problem constants
#define KC   1024
#define DD   64
#define BB   32
#define TT   2048
#define NV   (BB*TT)
#define QE   (BB*DD*TT)
#define DECAYF 0.99f
#define OMD    (1.0f - 0.99f)
#define COMMITF 0.25f
#define EPSF 1e-5f
#define NCAND 6

// Output layout (flat float32, reference tuple order)
#define OFF_Q      0
#define OFF_LOSS   (OFF_Q + QE)
#define OFF_CODES  (OFF_LOSS + 1)
#define OFF_NEWEMB (OFF_CODES + NV)
#define OFF_NEWCS  (OFF_NEWEMB + KC*DD)
#define OFF_NEWW   (OFF_NEWCS + KC)

// Scratch (device globals — no allocation)
__device__ float    g_hn[KC];        // fp32 exact half-norms (rescore)
__device__ uint16_t g_hnh[KC];       // fp16 half-norms (screen offset)
__device__ float    g_counts[KC];
__device__ float    g_dw[KC*DD];
__device__ float    g_loss;
__device__ __align__(256) uint16_t g_ehi[KC*DD];   // fp16 embedding

#define SWZ(o) ((o) ^ (((o) >> 3) & 0x70))

__device__ __forceinline__ uint32_t smem_u32(const void* p) {
    uint32_t a;
    asm("{ .reg .u64 t; cvta.to.shared.u64 t, %1; cvt.u32.u64 %0, t; }" : "=r"(a) : "l"(p));
    return a;
}

// fp16 MMA with fp16 accumulators: D(2 regs) = A(4) * B(2) + D
#define MMA_F16A(acc, A, B0, B1)                                               \
    asm volatile("mma.sync.aligned.m16n8k16.row.col.f16.f16.f16.f16 "          \
        "{%0,%1},{%2,%3,%4,%5},{%6,%7},{%0,%1};"                               \
        : "+r"((acc)[0]), "+r"((acc)[1])                                       \
        : "r"((A)[0]), "r"((A)[1]), "r"((A)[2]), "r"((A)[3]),                  \
          "r"(B0), "r"(B1))

#define HADD2(r, a, b)                                                         \
    asm("add.f16x2 %0, %1, %2;" : "=r"(r) : "r"(a), "r"(b))

#define CP_ASYNC16(dst_u32, src_ptr)                                           \
    asm volatile("cp.async.cg.shared.global [%0], [%1], 16;"                   \
                 :: "r"(dst_u32), "l"(src_ptr) : "memory")
#define CP_COMMIT() asm volatile("cp.async.commit_group;" ::: "memory")
#define CP_WAIT1()  asm volatile("cp.async.wait_group 1;" ::: "memory")
#define CP_WAIT0()  asm volatile("cp.async.wait_group 0;" ::: "memory")

// SMEM layout: A-fp16 16KB | B double buffer 2x16KB | hn-half2 2KB
#define SM_AH    0
#define SM_B     16384
#define SM_HN    49152
#define SM_CAND  SM_AH                  // reused after MMA loop
#define SM_TOTAL (SM_HN + 2048 + 128)

// ---------------------------------------------------------------------------
// Prep: zero scratch, fp16 embedding, warp-per-code half-norms
// ---------------------------------------------------------------------------
__global__ void vq_prep(const float* __restrict__ emb) {
    int i = blockIdx.x * 256 + threadIdx.x;   // 65536 threads
    g_dw[i] = 0.0f;
    {
        __half h = __float2half_rn(emb[i]);
        g_ehi[i] = reinterpret_cast<uint16_t&>(h);
    }
    int w = i >> 5;                            // global warp id (0..2047)
    int lane = i & 31;
    if (w < KC) {
        const float2* r = (const float2*)(emb + (size_t)w * DD);
        float2 v = r[lane];
        float s = v.x * v.x + v.y * v.y;
        #pragma unroll
        for (int o = 16; o; o >>= 1) s += __shfl_xor_sync(0xffffffffu, s, o);
        if (lane == 0) {
            float hn = 0.5f * s;
            g_hn[w] = hn;
            __half hh = __float2half_rn(hn);
            g_hnh[w] = reinterpret_cast<uint16_t&>(hh);
            g_counts[w] = 0.0f;
        }
    }
    if (i == 0) g_loss = 0.0f;
}

// ---------------------------------------------------------------------------
// Main: fp16-acc HMMA screen + lane top-3 + merged top-6 exact rescore
// ---------------------------------------------------------------------------
extern __shared__ __align__(1024) char smc[];

// Merge 2 new values into sorted ascending top-3 (v0<=v1<=v2). 9 FMNMX.
__device__ __forceinline__ void insp3(float v[3], float a, float b) {
    float a0 = fminf(a, b), a1 = fmaxf(a, b);
    float x0 = fminf(v[0], a0), y0 = fmaxf(v[0], a0);
    float x1 = fminf(v[1], a1), y1 = fmaxf(v[1], a1);
    v[0] = x0;
    v[1] = fminf(y0, x1);
    v[2] = fminf(fmaxf(y0, x1), fminf(v[2], y1));
}
__device__ __forceinline__ void ins6(float v[6], float w) {
    float t = w;
    #pragma unroll
    for (int i = 0; i < 6; ++i) {
        float lo = fminf(t, v[i]);
        t = fmaxf(t, v[i]);
        v[i] = lo;
    }
}
// Single LOP3: clear 10 low mantissa bits, insert index
__device__ __forceinline__ float packsi(float s, uint32_t idx) {
    return __uint_as_float((__float_as_uint(s) & 0xFFFFFC00u) | idx);
}

__device__ __forceinline__ void load_bchunk_async(uint32_t sb, int c, int buf, int tid) {
    #pragma unroll
    for (int i = 0; i < 8; ++i) {
        int idx  = tid + i * 128;            // 0..1023
        int code = idx >> 3;
        int ch   = idx & 7;
        const uint16_t* src = g_ehi + (size_t)(c * 128 + code) * DD + ch * 8;
        uint32_t doff = SM_B + buf * 16384 + code * 128 + ((ch ^ (code & 7)) * 16);
        CP_ASYNC16(sb + doff, src);
    }
}

__global__ __launch_bounds__(128, 4) void vq_main_mma(
        const float* __restrict__ z,
        const float* __restrict__ emb,
        float* __restrict__ out) {
    __shared__ float swr[4];
    const int tid  = threadIdx.x;
    const int wid  = tid >> 5;
    const int lane = tid & 31;
    const uint32_t sb = smem_u32(smc);

    const int n = blockIdx.x * 128 + tid;
    const int b = n >> 11;
    const int t = n & 2047;
    const float* zp = z + (size_t)b * (DD * TT) + t;

    // --- Stage A: load z (coalesced), NEGATED fp16, swizzled store
    #pragma unroll
    for (int d = 0; d < DD; d += 2) {
        __half h0 = __float2half_rn(-zp[(size_t)d * TT]);
        __half h1 = __float2half_rn(-zp[(size_t)(d + 1) * TT]);
        uint32_t hp = (uint32_t)reinterpret_cast<uint16_t&>(h0)
                    | ((uint32_t)reinterpret_cast<uint16_t&>(h1) << 16);
        uint32_t off = SWZ((uint32_t)(tid * 128 + 2 * d));
        *(uint32_t*)(smc + SM_AH + off) = hp;
    }
    // h table as half2 words (pairs of consecutive codes)
    uint32_t* shn2 = (uint32_t*)(smc + SM_HN);
    #pragma unroll
    for (int i = 0; i < 4; ++i)
        shn2[tid + i * 128] = ((const uint32_t*)g_hnh)[tid + i * 128];

    // Prefetch B chunks 0, 1
    load_bchunk_async(sb, 0, 0, tid); CP_COMMIT();
    load_bchunk_async(sb, 1, 1, tid); CP_COMMIT();

    __syncthreads();

    // --- A fragments: 2 m-tiles x 4 k-steps x 4 regs (hold -x, fp16)
    uint32_t ah[2][4][4];
    #pragma unroll
    for (int mt = 0; mt < 2; ++mt) {
        int base_r = wid * 32 + mt * 16;
        #pragma unroll
        for (int s = 0; s < 4; ++s) {
            #pragma unroll
            for (int q = 0; q < 4; ++q) {
                int row = base_r + (lane >> 2) + (q & 1) * 8;
                uint32_t off = SWZ((uint32_t)(row * 128 + s * 32
                                  + (lane & 3) * 4 + (q >> 1) * 16));
                ah[mt][s][q] = *(const uint32_t*)(smc + SM_AH + off);
            }
        }
    }

    // Per-slot sorted top-3 trackers (packed score|index floats)
    float tv[4][3];
    #pragma unroll
    for (int s = 0; s < 4; ++s)
        #pragma unroll
        for (int j = 0; j < 3; ++j) tv[s][j] = 1.0e38f;

    // --- Chunk loop: 8 chunks x 128 codes
    for (int c = 0; c < 8; ++c) {
        if (c < 7) CP_WAIT1(); else CP_WAIT0();
        __syncthreads();
        const char* bb = smc + SM_B + (c & 1) * 16384;

        #pragma unroll 1
        for (int nt = 0; nt < 16; ++nt) {
            int brow = nt * 8 + (lane >> 2);
            uint32_t bh[4][2];
            #pragma unroll
            for (int s = 0; s < 4; ++s) {
                uint32_t o0 = SWZ((uint32_t)(brow * 128 + s * 32 + (lane & 3) * 4));
                uint32_t o1 = SWZ((uint32_t)(brow * 128 + s * 32 + (lane & 3) * 4 + 16));
                bh[s][0] = *(const uint32_t*)(bb + o0);
                bh[s][1] = *(const uint32_t*)(bb + o1);
            }
            uint32_t c0 = (uint32_t)(c * 128 + nt * 8 + (lane & 3) * 2);
            uint32_t h01 = shn2[c * 64 + nt * 4 + (lane & 3)];
            // 4 independent 2-deep chains; h offset seeded in chain A
            uint32_t a0A[2] = {h01, h01}, a0B[2] = {0u, 0u};
            uint32_t a1A[2] = {h01, h01}, a1B[2] = {0u, 0u};
            MMA_F16A(a0A, ah[0][0], bh[0][0], bh[0][1]);
            MMA_F16A(a0B, ah[0][2], bh[2][0], bh[2][1]);
            MMA_F16A(a1A, ah[1][0], bh[0][0], bh[0][1]);
            MMA_F16A(a1B, ah[1][2], bh[2][0], bh[2][1]);
            MMA_F16A(a0A, ah[0][1], bh[1][0], bh[1][1]);
            MMA_F16A(a0B, ah[0][3], bh[3][0], bh[3][1]);
            MMA_F16A(a1A, ah[1][1], bh[1][0], bh[1][1]);
            MMA_F16A(a1B, ah[1][3], bh[3][0], bh[3][1]);
            uint32_t s00, s01, s10, s11;
            HADD2(s00, a0A[0], a0B[0]);   // mtile0, row      (scores c0, c0+1)
            HADD2(s01, a0A[1], a0B[1]);   // mtile0, row+8
            HADD2(s10, a1A[0], a1B[0]);   // mtile1, row
            HADD2(s11, a1A[1], a1B[1]);   // mtile1, row+8
            float2 f00 = __half22float2(*reinterpret_cast<__half2*>(&s00));
            float2 f01 = __half22float2(*reinterpret_cast<__half2*>(&s01));
            float2 f10 = __half22float2(*reinterpret_cast<__half2*>(&s10));
            float2 f11 = __half22float2(*reinterpret_cast<__half2*>(&s11));
            insp3(tv[0], packsi(f00.x, c0), packsi(f00.y, c0 + 1));
            insp3(tv[1], packsi(f01.x, c0), packsi(f01.y, c0 + 1));
            insp3(tv[2], packsi(f10.x, c0), packsi(f10.y, c0 + 1));
            insp3(tv[3], packsi(f11.x, c0), packsi(f11.y, c0 + 1));
        }
        __syncthreads();
        if (c < 6) { load_bchunk_async(sb, c + 2, c & 1, tid); CP_COMMIT(); }
    }

    // --- Cross-lane butterfly merge (4 lanes, disjoint code sets) -> top-6
    int* ci = (int*)(smc + SM_CAND);
    #pragma unroll
    for (int s = 0; s < 4; ++s) {
        float m[6] = {tv[s][0], tv[s][1], tv[s][2], 1.0e38f, 1.0e38f, 1.0e38f};
        #pragma unroll
        for (int off = 1; off <= 2; off <<= 1) {
            float p[6];
            #pragma unroll
            for (int j = 0; j < 6; ++j) p[j] = __shfl_xor_sync(0xffffffffu, m[j], off);
            #pragma unroll
            for (int j = 0; j < 6; ++j) ins6(m, p[j]);
        }
        if ((lane & 3) == 0) {
            int row = wid * 32 + (s >> 1) * 16 + (s & 1) * 8 + (lane >> 2);
            #pragma unroll
            for (int j = 0; j < NCAND; ++j)
                ci[row * NCAND + j] = (int)(__float_as_uint(m[j]) & 1023u);
        }
    }
    __syncthreads();

    // --- Load x into registers (coalesced), exact fp32 rescore of 6 cands
    float xr[DD];
    #pragma unroll
    for (int d = 0; d < DD; ++d) xr[d] = zp[(size_t)d * TT];

    float bestv = 3.4e38f;
    int   besti = 0;
    #pragma unroll
    for (int j = 0; j < NCAND; ++j) {
        int idx = ci[tid * NCAND + j];
        const float4* er = (const float4*)(emb + (size_t)idx * DD);
        float dot = 0.0f;
        #pragma unroll
        for (int q = 0; q < 16; ++q) {
            float4 e4 = __ldg(er + q);
            dot = fmaf(xr[4 * q + 0], e4.x, dot);
            dot = fmaf(xr[4 * q + 1], e4.y, dot);
            dot = fmaf(xr[4 * q + 2], e4.z, dot);
            dot = fmaf(xr[4 * q + 3], e4.w, dot);
        }
        float v = g_hn[idx] - dot;
        if (v < bestv || (v == bestv && idx < besti)) { bestv = v; besti = idx; }
    }

    // --- Epilogue: quantized write, loss, codes, segment sums
    const float4* er = (const float4*)(emb + (size_t)besti * DD);
    float* oq = out + OFF_Q + (size_t)b * (DD * TT) + t;
    float* dwp = g_dw + (size_t)besti * DD;
    float lsum = 0.0f;
    #pragma unroll
    for (int j = 0; j < 16; ++j) {
        float4 e4 = __ldg(er + j);
        float x0 = xr[4 * j + 0], x1 = xr[4 * j + 1];
        float x2 = xr[4 * j + 2], x3 = xr[4 * j + 3];
        oq[(size_t)(4 * j + 0) * TT] = e4.x;
        oq[(size_t)(4 * j + 1) * TT] = e4.y;
        oq[(size_t)(4 * j + 2) * TT] = e4.z;
        oq[(size_t)(4 * j + 3) * TT] = e4.w;
        float q0 = e4.x - x0, q1 = e4.y - x1, q2 = e4.z - x2, q3 = e4.w - x3;
        lsum += q0 * q0 + q1 * q1 + q2 * q2 + q3 * q3;
        asm volatile("red.global.add.v4.f32 [%0], {%1,%2,%3,%4};"
                     :: "l"(dwp + 4 * j), "f"(x0), "f"(x1), "f"(x2), "f"(x3) : "memory");
    }
    out[OFF_CODES + n] = (float)besti;
    atomicAdd(&g_counts[besti], 1.0f);

    #pragma unroll
    for (int o = 16; o; o >>= 1) lsum += __shfl_xor_sync(0xffffffffu, lsum, o);
    if (lane == 0) swr[wid] = lsum;
    __syncthreads();
    if (tid == 0)
        atomicAdd(&g_loss, swr[0] + swr[1] + swr[2] + swr[3]);
}

// ---------------------------------------------------------------------------
// Finalize (merged): per-block nsum reduction, new_cs/loss (block 0),
// new_w + new_embedding everywhere.  256 blocks x 256 threads.
// ---------------------------------------------------------------------------
__global__ __launch_bounds__(256) void vq_fin(
        const float* __restrict__ ema_cs,
        const float* __restrict__ ema_w,
        float* __restrict__ out) {
    __shared__ float sw[8];
    __shared__ float snv;
    int tid = threadIdx.x;
    int i = blockIdx.x * 256 + tid;

    float s = 0.0f;
    #pragma unroll
    for (int j = 0; j < 4; ++j) {
        int k = tid * 4 + j;
        s += DECAYF * ema_cs[k] + OMD * g_counts[k];
    }
    #pragma unroll
    for (int o = 16; o; o >>= 1) s += __shfl_xor_sync(0xffffffffu, s, o);
    if ((tid & 31) == 0) sw[tid >> 5] = s;
    __syncthreads();
    if (tid < 32) {
        float u = (tid < 8) ? sw[tid] : 0.0f;
        #pragma unroll
        for (int o = 4; o; o >>= 1) u += __shfl_xor_sync(0xffffffffu, u, o);
        if (tid == 0) snv = u;
    }
    __syncthreads();
    float nsum = snv;

    if (blockIdx.x == 0) {
        #pragma unroll
        for (int j = 0; j < 4; ++j) {
            int k = tid * 4 + j;
            out[OFF_NEWCS + k] = DECAYF * ema_cs[k] + OMD * g_counts[k];
        }
        if (tid == 0) out[OFF_LOSS] = COMMITF * g_loss * (1.0f / (float)QE);
    }

    int k = i >> 6;
    float cs = DECAYF * ema_cs[k] + OMD * g_counts[k];
    float cluster = (cs + EPSF) / (nsum + (float)KC * EPSF) * nsum;
    float nw = DECAYF * ema_w[i] + OMD * g_dw[i];
    out[OFF_NEWW + i] = nw;
    out[OFF_NEWEMB + i] = nw * (1.0f / cluster);
}

// ---------------------------------------------------------------------------
extern "C" void kernel_launch(void* const* d_in, const int* in_sizes, int n_in,
                              void* d_out, int out_size) {
    const float* z      = (const float*)d_in[0];
    const float* emb    = (const float*)d_in[1];
    const float* ema_cs = (const float*)d_in[2];
    const float* ema_w  = (const float*)d_in[3];
    float* out = (float*)d_out;

    cudaFuncSetAttribute(vq_main_mma, cudaFuncAttributeMaxDynamicSharedMemorySize, SM_TOTAL);

    vq_prep<<<256, 256>>>(emb);
    vq_main_mma<<<512, 128, SM_TOTAL>>>(z, emb, out);
    vq_fin<<<256, 256>>>(ema_cs, ema_w, out);
}

// round 10
// speedup vs baseline: 1.3305x; 1.0994x over previous
#include <cuda_runtime.h>
#include <cuda_fp16.h>
#include <cstdint>

// Problem constants
#define KC   1024
#define DD   64
#define BB   32
#define TT   2048
#define NV   (BB*TT)
#define QE   (BB*DD*TT)
#define DECAYF 0.99f
#define OMD    (1.0f - 0.99f)
#define COMMITF 0.25f
#define EPSF 1e-5f
#define NCAND 6

// Output layout (flat float32, reference tuple order)
#define OFF_Q      0
#define OFF_LOSS   (OFF_Q + QE)
#define OFF_CODES  (OFF_LOSS + 1)
#define OFF_NEWEMB (OFF_CODES + NV)
#define OFF_NEWCS  (OFF_NEWEMB + KC*DD)
#define OFF_NEWW   (OFF_NEWCS + KC)

// Scratch (device globals — no allocation)
__device__ float    g_hn[KC];        // fp32 exact half-norms (rescore)
__device__ uint16_t g_hnh[KC];       // fp16 half-norms (screen offset)
__device__ float    g_counts[KC];
__device__ float    g_dw[KC*DD];
__device__ float    g_loss;
__device__ __align__(256) uint16_t g_ehi[KC*DD];   // fp16 embedding

#define SWZ(o) ((o) ^ (((o) >> 3) & 0x70))

__device__ __forceinline__ uint32_t smem_u32(const void* p) {
    uint32_t a;
    asm("{ .reg .u64 t; cvta.to.shared.u64 t, %1; cvt.u32.u64 %0, t; }" : "=r"(a) : "l"(p));
    return a;
}

// fp16 MMA with fp16 accumulators: D(2 regs) = A(4) * B(2) + D
#define MMA_F16A(acc, A, B0, B1)                                               \
    asm volatile("mma.sync.aligned.m16n8k16.row.col.f16.f16.f16.f16 "          \
        "{%0,%1},{%2,%3,%4,%5},{%6,%7},{%0,%1};"                               \
        : "+r"((acc)[0]), "+r"((acc)[1])                                       \
        : "r"((A)[0]), "r"((A)[1]), "r"((A)[2]), "r"((A)[3]),                  \
          "r"(B0), "r"(B1))

#define HADD2(r, a, b)                                                         \
    asm("add.f16x2 %0, %1, %2;" : "=r"(r) : "r"(a), "r"(b))

#define CP_ASYNC16(dst_u32, src_ptr)                                           \
    asm volatile("cp.async.cg.shared.global [%0], [%1], 16;"                   \
                 :: "r"(dst_u32), "l"(src_ptr) : "memory")
#define CP_COMMIT() asm volatile("cp.async.commit_group;" ::: "memory")
#define CP_WAIT1()  asm volatile("cp.async.wait_group 1;" ::: "memory")
#define CP_WAIT0()  asm volatile("cp.async.wait_group 0;" ::: "memory")

// SMEM layout: A-fp16 8KB | B double buffer 2x8KB | hn-half2 2KB
#define SM_AH    0
#define SM_B     8192
#define SM_HN    24576
#define SM_CAND  SM_AH                  // reused after MMA loop (64*6 ints)
#define SM_TOTAL (SM_HN + 2048 + 128)   // 26752

// ---------------------------------------------------------------------------
// Prep: zero scratch, fp16 embedding, warp-per-code half-norms
// ---------------------------------------------------------------------------
__global__ void vq_prep(const float* __restrict__ emb) {
    int i = blockIdx.x * 256 + threadIdx.x;   // 65536 threads
    g_dw[i] = 0.0f;
    {
        __half h = __float2half_rn(emb[i]);
        g_ehi[i] = reinterpret_cast<uint16_t&>(h);
    }
    int w = i >> 5;                            // global warp id (0..2047)
    int lane = i & 31;
    if (w < KC) {
        const float2* r = (const float2*)(emb + (size_t)w * DD);
        float2 v = r[lane];
        float s = v.x * v.x + v.y * v.y;
        #pragma unroll
        for (int o = 16; o; o >>= 1) s += __shfl_xor_sync(0xffffffffu, s, o);
        if (lane == 0) {
            float hn = 0.5f * s;
            g_hn[w] = hn;
            __half hh = __float2half_rn(hn);
            g_hnh[w] = reinterpret_cast<uint16_t&>(hh);
            g_counts[w] = 0.0f;
        }
    }
    if (i == 0) g_loss = 0.0f;
}

// ---------------------------------------------------------------------------
// Main: fp16-acc HMMA screen, M=64/CTA, grid 1024, occupancy 8
// ---------------------------------------------------------------------------
extern __shared__ __align__(1024) char smc[];

// Merge 2 new values into sorted ascending top-3 (v0<=v1<=v2). 9 FMNMX.
__device__ __forceinline__ void insp3(float v[3], float a, float b) {
    float a0 = fminf(a, b), a1 = fmaxf(a, b);
    float x0 = fminf(v[0], a0), y0 = fmaxf(v[0], a0);
    float x1 = fminf(v[1], a1), y1 = fmaxf(v[1], a1);
    v[0] = x0;
    v[1] = fminf(y0, x1);
    v[2] = fminf(fmaxf(y0, x1), fminf(v[2], y1));
}
__device__ __forceinline__ void ins6(float v[6], float w) {
    float t = w;
    #pragma unroll
    for (int i = 0; i < 6; ++i) {
        float lo = fminf(t, v[i]);
        t = fmaxf(t, v[i]);
        v[i] = lo;
    }
}
__device__ __forceinline__ float packsi(float s, uint32_t idx) {
    return __uint_as_float((__float_as_uint(s) & 0xFFFFFC00u) | idx);
}

// Load one 64-code B chunk (8KB) into buf
__device__ __forceinline__ void load_bchunk_async(uint32_t sb, int c, int buf, int tid) {
    #pragma unroll
    for (int i = 0; i < 4; ++i) {
        int idx  = tid + i * 128;            // 0..511
        int code = idx >> 3;                 // 0..63
        int ch   = idx & 7;
        const uint16_t* src = g_ehi + (size_t)(c * 64 + code) * DD + ch * 8;
        uint32_t doff = SM_B + buf * 8192 + code * 128 + ((ch ^ (code & 7)) * 16);
        CP_ASYNC16(sb + doff, src);
    }
}

__global__ __launch_bounds__(128, 8) void vq_main_mma(
        const float* __restrict__ z,
        const float* __restrict__ emb,
        float* __restrict__ out) {
    __shared__ float swr[4];
    const int tid  = threadIdx.x;
    const int wid  = tid >> 5;
    const int lane = tid & 31;
    const uint32_t sb = smem_u32(smc);

    const int n0 = blockIdx.x * 64;          // first vector of this CTA
    const int b  = n0 >> 11;
    const int t0 = n0 & 2047;
    const float* zb = z + (size_t)b * (DD * TT) + t0;

    // --- Stage A: 2 threads per row, each 32 dims; NEGATED fp16, swizzled
    {
        int r  = tid & 63;
        int hf = tid >> 6;                   // dim half
        const float* zr = zb + r;
        #pragma unroll
        for (int j = 0; j < 16; ++j) {
            int d = hf * 32 + 2 * j;
            __half h0 = __float2half_rn(-zr[(size_t)d * TT]);
            __half h1 = __float2half_rn(-zr[(size_t)(d + 1) * TT]);
            uint32_t hp = (uint32_t)reinterpret_cast<uint16_t&>(h0)
                        | ((uint32_t)reinterpret_cast<uint16_t&>(h1) << 16);
            *(uint32_t*)(smc + SM_AH + SWZ((uint32_t)(r * 128 + 2 * d))) = hp;
        }
    }
    // hn table as half2 words
    uint32_t* shn2 = (uint32_t*)(smc + SM_HN);
    #pragma unroll
    for (int i = 0; i < 4; ++i)
        shn2[tid + i * 128] = ((const uint32_t*)g_hnh)[tid + i * 128];

    // Prefetch B chunks 0, 1
    load_bchunk_async(sb, 0, 0, tid); CP_COMMIT();
    load_bchunk_async(sb, 1, 1, tid); CP_COMMIT();

    __syncthreads();

    // --- A fragments: 1 m-tile per warp (rows wid*16..+15), 4 k-steps x 4 regs
    uint32_t ah[4][4];
    #pragma unroll
    for (int s = 0; s < 4; ++s) {
        #pragma unroll
        for (int q = 0; q < 4; ++q) {
            int row = wid * 16 + (lane >> 2) + (q & 1) * 8;
            uint32_t off = SWZ((uint32_t)(row * 128 + s * 32
                              + (lane & 3) * 4 + (q >> 1) * 16));
            ah[s][q] = *(const uint32_t*)(smc + SM_AH + off);
        }
    }

    // Per-slot sorted top-3 trackers (packed score|index floats)
    float tv[2][3];
    #pragma unroll
    for (int s = 0; s < 2; ++s)
        #pragma unroll
        for (int j = 0; j < 3; ++j) tv[s][j] = 1.0e38f;

    // --- Chunk loop: 16 chunks x 64 codes
    #pragma unroll 1
    for (int c = 0; c < 16; ++c) {
        if (c < 15) CP_WAIT1(); else CP_WAIT0();
        __syncthreads();
        const char* bb = smc + SM_B + (c & 1) * 8192;

        #pragma unroll 1
        for (int nt = 0; nt < 8; ++nt) {
            int brow = nt * 8 + (lane >> 2);
            uint32_t bh[4][2];
            #pragma unroll
            for (int s = 0; s < 4; ++s) {
                uint32_t o0 = SWZ((uint32_t)(brow * 128 + s * 32 + (lane & 3) * 4));
                uint32_t o1 = SWZ((uint32_t)(brow * 128 + s * 32 + (lane & 3) * 4 + 16));
                bh[s][0] = *(const uint32_t*)(bb + o0);
                bh[s][1] = *(const uint32_t*)(bb + o1);
            }
            uint32_t c0 = (uint32_t)(c * 64 + nt * 8 + (lane & 3) * 2);
            uint32_t h01 = shn2[c * 32 + nt * 4 + (lane & 3)];
            // 2 independent 2-deep chains; h offset seeded in chain A
            uint32_t aA[2] = {h01, h01}, aB[2] = {0u, 0u};
            MMA_F16A(aA, ah[0], bh[0][0], bh[0][1]);
            MMA_F16A(aB, ah[2], bh[2][0], bh[2][1]);
            MMA_F16A(aA, ah[1], bh[1][0], bh[1][1]);
            MMA_F16A(aB, ah[3], bh[3][0], bh[3][1]);
            uint32_t s0, s1;
            HADD2(s0, aA[0], aB[0]);   // row lane>>2       (scores c0, c0+1)
            HADD2(s1, aA[1], aB[1]);   // row lane>>2 + 8
            float2 f0 = __half22float2(*reinterpret_cast<__half2*>(&s0));
            float2 f1 = __half22float2(*reinterpret_cast<__half2*>(&s1));
            insp3(tv[0], packsi(f0.x, c0), packsi(f0.y, c0 + 1));
            insp3(tv[1], packsi(f1.x, c0), packsi(f1.y, c0 + 1));
        }
        __syncthreads();
        if (c < 14) { load_bchunk_async(sb, c + 2, c & 1, tid); CP_COMMIT(); }
    }

    // --- Cross-lane butterfly merge (4 lanes, disjoint code sets) -> top-6
    int* ci = (int*)(smc + SM_CAND);
    #pragma unroll
    for (int s = 0; s < 2; ++s) {
        float m[6] = {tv[s][0], tv[s][1], tv[s][2], 1.0e38f, 1.0e38f, 1.0e38f};
        #pragma unroll
        for (int off = 1; off <= 2; off <<= 1) {
            float p[6];
            #pragma unroll
            for (int j = 0; j < 6; ++j) p[j] = __shfl_xor_sync(0xffffffffu, m[j], off);
            #pragma unroll
            for (int j = 0; j < 6; ++j) ins6(m, p[j]);
        }
        if ((lane & 3) == 0) {
            int row = wid * 16 + s * 8 + (lane >> 2);
            #pragma unroll
            for (int j = 0; j < NCAND; ++j)
                ci[row * NCAND + j] = (int)(__float_as_uint(m[j]) & 1023u);
        }
    }
    __syncthreads();

    // --- Epilogue: 2 threads per row, each owns 32 dims
    const int row = tid >> 1;
    const int hh  = tid & 1;
    const float* zr = zb + row;

    // z half in registers (32 regs), reused by rescore + loss + dw
    float zh[32];
    #pragma unroll
    for (int k = 0; k < 32; ++k) zh[k] = zr[(size_t)(hh * 32 + k) * TT];

    // Exact fp32 rescore of 6 candidates (split over dim halves, shfl combine)
    float bestv = 3.4e38f;
    int   besti = 0;
    #pragma unroll
    for (int j = 0; j < NCAND; ++j) {
        int idx = ci[row * NCAND + j];
        const float4* er = (const float4*)(emb + (size_t)idx * DD + hh * 32);
        float dot = 0.0f;
        #pragma unroll
        for (int q = 0; q < 8; ++q) {
            float4 e4 = __ldg(er + q);
            dot = fmaf(zh[4 * q + 0], e4.x, dot);
            dot = fmaf(zh[4 * q + 1], e4.y, dot);
            dot = fmaf(zh[4 * q + 2], e4.z, dot);
            dot = fmaf(zh[4 * q + 3], e4.w, dot);
        }
        dot += __shfl_xor_sync(0xffffffffu, dot, 1);
        float v = g_hn[idx] - dot;
        if (v < bestv || (v == bestv && idx < besti)) { bestv = v; besti = idx; }
    }

    // Quantized write + loss + dw for own half
    const float4* er = (const float4*)(emb + (size_t)besti * DD + hh * 32);
    float* oq = out + OFF_Q + (size_t)b * (DD * TT) + t0 + row;
    float* dwp = g_dw + (size_t)besti * DD + hh * 32;
    float lsum = 0.0f;
    #pragma unroll
    for (int q = 0; q < 8; ++q) {
        float4 e4 = __ldg(er + q);
        int d = hh * 32 + 4 * q;
        oq[(size_t)(d + 0) * TT] = e4.x;
        oq[(size_t)(d + 1) * TT] = e4.y;
        oq[(size_t)(d + 2) * TT] = e4.z;
        oq[(size_t)(d + 3) * TT] = e4.w;
        float q0 = e4.x - zh[4 * q + 0], q1 = e4.y - zh[4 * q + 1];
        float q2 = e4.z - zh[4 * q + 2], q3 = e4.w - zh[4 * q + 3];
        lsum += q0 * q0 + q1 * q1 + q2 * q2 + q3 * q3;
        asm volatile("red.global.add.v4.f32 [%0], {%1,%2,%3,%4};"
                     :: "l"(dwp + 4 * q),
                        "f"(zh[4 * q + 0]), "f"(zh[4 * q + 1]),
                        "f"(zh[4 * q + 2]), "f"(zh[4 * q + 3]) : "memory");
    }
    if (hh == 0) {
        out[OFF_CODES + n0 + row] = (float)besti;
        atomicAdd(&g_counts[besti], 1.0f);
    }

    #pragma unroll
    for (int o = 16; o; o >>= 1) lsum += __shfl_xor_sync(0xffffffffu, lsum, o);
    if (lane == 0) swr[wid] = lsum;
    __syncthreads();
    if (tid == 0)
        atomicAdd(&g_loss, swr[0] + swr[1] + swr[2] + swr[3]);
}

// ---------------------------------------------------------------------------
// Finalize (merged): per-block nsum reduction, new_cs/loss (block 0),
// new_w + new_embedding everywhere.  256 blocks x 256 threads.
// ---------------------------------------------------------------------------
__global__ __launch_bounds__(256) void vq_fin(
        const float* __restrict__ ema_cs,
        const float* __restrict__ ema_w,
        float* __restrict__ out) {
    __shared__ float sw[8];
    __shared__ float snv;
    int tid = threadIdx.x;
    int i = blockIdx.x * 256 + tid;

    float s = 0.0f;
    #pragma unroll
    for (int j = 0; j < 4; ++j) {
        int k = tid * 4 + j;
        s += DECAYF * ema_cs[k] + OMD * g_counts[k];
    }
    #pragma unroll
    for (int o = 16; o; o >>= 1) s += __shfl_xor_sync(0xffffffffu, s, o);
    if ((tid & 31) == 0) sw[tid >> 5] = s;
    __syncthreads();
    if (tid < 32) {
        float u = (tid < 8) ? sw[tid] : 0.0f;
        #pragma unroll
        for (int o = 4; o; o >>= 1) u += __shfl_xor_sync(0xffffffffu, u, o);
        if (tid == 0) snv = u;
    }
    __syncthreads();
    float nsum = snv;

    if (blockIdx.x == 0) {
        #pragma unroll
        for (int j = 0; j < 4; ++j) {
            int k = tid * 4 + j;
            out[OFF_NEWCS + k] = DECAYF * ema_cs[k] + OMD * g_counts[k];
        }
        if (tid == 0) out[OFF_LOSS] = COMMITF * g_loss * (1.0f / (float)QE);
    }

    int k = i >> 6;
    float cs = DECAYF * ema_cs[k] + OMD * g_counts[k];
    float cluster = (cs + EPSF) / (nsum + (float)KC * EPSF) * nsum;
    float nw = DECAYF * ema_w[i] + OMD * g_dw[i];
    out[OFF_NEWW + i] = nw;
    out[OFF_NEWEMB + i] = nw * (1.0f / cluster);
}

// ---------------------------------------------------------------------------
extern "C" void kernel_launch(void* const* d_in, const int* in_sizes, int n_in,
                              void* d_out, int out_size) {
    const float* z      = (const float*)d_in[0];
    const float* emb    = (const float*)d_in[1];
    const float* ema_cs = (const float*)d_in[2];
    const float* ema_w  = (const float*)d_in[3];
    float* out = (float*)d_out;

    cudaFuncSetAttribute(vq_main_mma, cudaFuncAttributeMaxDynamicSharedMemorySize, SM_TOTAL);

    vq_prep<<<256, 256>>>(emb);
    vq_main_mma<<<1024, 128, SM_TOTAL>>>(z, emb, out);
    vq_fin<<<256, 256>>>(ema_cs, ema_w, out);
}

// round 11
// speedup vs baseline: 1.4582x; 1.0960x over previous
#include <cuda_runtime.h>
#include <cuda_fp16.h>
#include <cstdint>

// Problem constants
#define KC   1024
#define DD   64
#define BB   32
#define TT   2048
#define NV   (BB*TT)
#define QE   (BB*DD*TT)
#define DECAYF 0.99f
#define OMD    (1.0f - 0.99f)
#define COMMITF 0.25f
#define EPSF 1e-5f
#define NCAND 6

// Output layout (flat float32, reference tuple order)
#define OFF_Q      0
#define OFF_LOSS   (OFF_Q + QE)
#define OFF_CODES  (OFF_LOSS + 1)
#define OFF_NEWEMB (OFF_CODES + NV)
#define OFF_NEWCS  (OFF_NEWEMB + KC*DD)
#define OFF_NEWW   (OFF_NEWCS + KC)

// Scratch (device globals — no allocation)
__device__ float    g_hn[KC];        // fp32 exact half-norms (rescore)
__device__ uint16_t g_hnh[KC];       // fp16 half-norms (screen offset)
__device__ float    g_counts[KC];
__device__ float    g_dw[KC*DD];
__device__ float    g_loss;
__device__ __align__(256) uint16_t g_ehi[KC*DD];   // fp16 embedding

#define SWZ(o) ((o) ^ (((o) >> 3) & 0x70))

__device__ __forceinline__ uint32_t smem_u32(const void* p) {
    uint32_t a;
    asm("{ .reg .u64 t; cvta.to.shared.u64 t, %1; cvt.u32.u64 %0, t; }" : "=r"(a) : "l"(p));
    return a;
}

// fp16 MMA with fp16 accumulators: D(2 regs) = A(4) * B(2) + D
#define MMA_F16A(acc, A, B0, B1)                                               \
    asm volatile("mma.sync.aligned.m16n8k16.row.col.f16.f16.f16.f16 "          \
        "{%0,%1},{%2,%3,%4,%5},{%6,%7},{%0,%1};"                               \
        : "+r"((acc)[0]), "+r"((acc)[1])                                       \
        : "r"((A)[0]), "r"((A)[1]), "r"((A)[2]), "r"((A)[3]),                  \
          "r"(B0), "r"(B1))

#define HADD2(r, a, b)                                                         \
    asm("add.f16x2 %0, %1, %2;" : "=r"(r) : "r"(a), "r"(b))

#define LDSM4(r0, r1, r2, r3, a)                                               \
    asm volatile("ldmatrix.sync.aligned.m8n8.x4.shared.b16 {%0,%1,%2,%3}, [%4];" \
        : "=r"(r0), "=r"(r1), "=r"(r2), "=r"(r3) : "r"(a))

#define CP_ASYNC16(dst_u32, src_ptr)                                           \
    asm volatile("cp.async.cg.shared.global [%0], [%1], 16;"                   \
                 :: "r"(dst_u32), "l"(src_ptr) : "memory")
#define CP_COMMIT() asm volatile("cp.async.commit_group;" ::: "memory")
#define CP_WAIT1()  asm volatile("cp.async.wait_group 1;" ::: "memory")
#define CP_WAIT0()  asm volatile("cp.async.wait_group 0;" ::: "memory")

// SMEM layout: A-fp16 8KB | B double buffer 2x8KB | hn-half2 2KB
#define SM_AH    0
#define SM_B     8192
#define SM_HN    24576
#define SM_CAND  SM_AH                  // reused after MMA loop (64*6 ints)
#define SM_TOTAL (SM_HN + 2048 + 128)   // 26752

// ---------------------------------------------------------------------------
// Prep: zero scratch, fp16 embedding, warp-per-code half-norms
// ---------------------------------------------------------------------------
__global__ void vq_prep(const float* __restrict__ emb) {
    int i = blockIdx.x * 256 + threadIdx.x;   // 65536 threads
    g_dw[i] = 0.0f;
    {
        __half h = __float2half_rn(emb[i]);
        g_ehi[i] = reinterpret_cast<uint16_t&>(h);
    }
    int w = i >> 5;                            // global warp id (0..2047)
    int lane = i & 31;
    if (w < KC) {
        const float2* r = (const float2*)(emb + (size_t)w * DD);
        float2 v = r[lane];
        float s = v.x * v.x + v.y * v.y;
        #pragma unroll
        for (int o = 16; o; o >>= 1) s += __shfl_xor_sync(0xffffffffu, s, o);
        if (lane == 0) {
            float hn = 0.5f * s;
            g_hn[w] = hn;
            __half hh = __float2half_rn(hn);
            g_hnh[w] = reinterpret_cast<uint16_t&>(hh);
            g_counts[w] = 0.0f;
        }
    }
    if (i == 0) g_loss = 0.0f;
}

// ---------------------------------------------------------------------------
// Main: fp16-acc HMMA screen, ldmatrix B loads, M=64/CTA, grid 1024, occ 8
// ---------------------------------------------------------------------------
extern __shared__ __align__(1024) char smc[];

// Merge 2 new values into sorted ascending top-3 (v0<=v1<=v2). 9 FMNMX.
__device__ __forceinline__ void insp3(float v[3], float a, float b) {
    float a0 = fminf(a, b), a1 = fmaxf(a, b);
    float x0 = fminf(v[0], a0), y0 = fmaxf(v[0], a0);
    float x1 = fminf(v[1], a1), y1 = fmaxf(v[1], a1);
    v[0] = x0;
    v[1] = fminf(y0, x1);
    v[2] = fminf(fmaxf(y0, x1), fminf(v[2], y1));
}
__device__ __forceinline__ void ins6(float v[6], float w) {
    float t = w;
    #pragma unroll
    for (int i = 0; i < 6; ++i) {
        float lo = fminf(t, v[i]);
        t = fmaxf(t, v[i]);
        v[i] = lo;
    }
}
__device__ __forceinline__ float packsi(float s, uint32_t idx) {
    return __uint_as_float((__float_as_uint(s) & 0xFFFFFC00u) | idx);
}

// Load one 64-code B chunk (8KB) into buf
__device__ __forceinline__ void load_bchunk_async(uint32_t sb, int c, int buf, int tid) {
    #pragma unroll
    for (int i = 0; i < 4; ++i) {
        int idx  = tid + i * 128;            // 0..511
        int code = idx >> 3;                 // 0..63
        int ch   = idx & 7;
        const uint16_t* src = g_ehi + (size_t)(c * 64 + code) * DD + ch * 8;
        uint32_t doff = SM_B + buf * 8192 + code * 128 + ((ch ^ (code & 7)) * 16);
        CP_ASYNC16(sb + doff, src);
    }
}

__global__ __launch_bounds__(128, 8) void vq_main_mma(
        const float* __restrict__ z,
        const float* __restrict__ emb,
        float* __restrict__ out) {
    __shared__ float swr[4];
    const int tid  = threadIdx.x;
    const int wid  = tid >> 5;
    const int lane = tid & 31;
    const uint32_t sb = smem_u32(smc);

    const int n0 = blockIdx.x * 64;          // first vector of this CTA
    const int b  = n0 >> 11;
    const int t0 = n0 & 2047;
    const float* zb = z + (size_t)b * (DD * TT) + t0;

    // --- Stage A: 2 threads per row, each 32 dims; NEGATED fp16, swizzled
    {
        int r  = tid & 63;
        int hf = tid >> 6;                   // dim half
        const float* zr = zb + r;
        #pragma unroll
        for (int j = 0; j < 16; ++j) {
            int d = hf * 32 + 2 * j;
            __half h0 = __float2half_rn(-zr[(size_t)d * TT]);
            __half h1 = __float2half_rn(-zr[(size_t)(d + 1) * TT]);
            uint32_t hp = (uint32_t)reinterpret_cast<uint16_t&>(h0)
                        | ((uint32_t)reinterpret_cast<uint16_t&>(h1) << 16);
            *(uint32_t*)(smc + SM_AH + SWZ((uint32_t)(r * 128 + 2 * d))) = hp;
        }
    }
    // hn table as half2 words
    uint32_t* shn2 = (uint32_t*)(smc + SM_HN);
    #pragma unroll
    for (int i = 0; i < 4; ++i)
        shn2[tid + i * 128] = ((const uint32_t*)g_hnh)[tid + i * 128];

    // Prefetch B chunks 0, 1
    load_bchunk_async(sb, 0, 0, tid); CP_COMMIT();
    load_bchunk_async(sb, 1, 1, tid); CP_COMMIT();

    __syncthreads();

    // ldmatrix lane constants
    const uint32_t r7 = (uint32_t)(lane & 7);
    const uint32_t mm = (uint32_t)(lane >> 3);

    // --- A fragments via 4x ldmatrix.x4: 1 m-tile/warp, 4 k-steps x 4 regs
    // mat m of x4: rowhalf = m&1, khalf = m>>1  ->  matches ah[s][q] layout
    uint32_t ah[4][4];
    {
        uint32_t arow = (uint32_t)(wid * 16) + (mm & 1) * 8 + r7;
        uint32_t acol = (mm >> 1) * 16;
        #pragma unroll
        for (int s = 0; s < 4; ++s) {
            uint32_t addr = sb + SM_AH + arow * 128
                          + (((uint32_t)(s * 32) + acol) ^ (r7 * 16));
            LDSM4(ah[s][0], ah[s][1], ah[s][2], ah[s][3], addr);
        }
    }

    // B ldmatrix per-lane constant offset within a chunk buffer:
    // mat m covers k-half m; addr = base + nt*1024 + r7*128 + (m*16 ^ r7*16)
    const uint32_t blconst = r7 * 128 + ((mm * 16) ^ (r7 * 16));

    // Per-slot sorted top-3 trackers (packed score|index floats)
    float tv[2][3];
    #pragma unroll
    for (int s = 0; s < 2; ++s)
        #pragma unroll
        for (int j = 0; j < 3; ++j) tv[s][j] = 1.0e38f;

    // --- Chunk loop: 16 chunks x 64 codes
    #pragma unroll 1
    for (int c = 0; c < 16; ++c) {
        if (c < 15) CP_WAIT1(); else CP_WAIT0();
        __syncthreads();
        const uint32_t bbase = sb + SM_B + (uint32_t)((c & 1) * 8192) + blconst;

        #pragma unroll 1
        for (int nt = 0; nt < 8; ++nt) {
            uint32_t a1 = bbase + (uint32_t)(nt * 1024);
            uint32_t a2 = a1 ^ 64u;
            uint32_t bh[4][2];
            LDSM4(bh[0][0], bh[0][1], bh[1][0], bh[1][1], a1);  // k-halves 0-3
            LDSM4(bh[2][0], bh[2][1], bh[3][0], bh[3][1], a2);  // k-halves 4-7

            uint32_t c0 = (uint32_t)(c * 64 + nt * 8 + (lane & 3) * 2);
            uint32_t h01 = shn2[c * 32 + nt * 4 + (lane & 3)];
            // 2 independent 2-deep chains; h offset seeded in chain A
            uint32_t aA[2] = {h01, h01}, aB[2] = {0u, 0u};
            MMA_F16A(aA, ah[0], bh[0][0], bh[0][1]);
            MMA_F16A(aB, ah[2], bh[2][0], bh[2][1]);
            MMA_F16A(aA, ah[1], bh[1][0], bh[1][1]);
            MMA_F16A(aB, ah[3], bh[3][0], bh[3][1]);
            uint32_t s0, s1;
            HADD2(s0, aA[0], aB[0]);   // row lane>>2       (scores c0, c0+1)
            HADD2(s1, aA[1], aB[1]);   // row lane>>2 + 8
            float2 f0 = __half22float2(*reinterpret_cast<__half2*>(&s0));
            float2 f1 = __half22float2(*reinterpret_cast<__half2*>(&s1));
            insp3(tv[0], packsi(f0.x, c0), packsi(f0.y, c0 + 1));
            insp3(tv[1], packsi(f1.x, c0), packsi(f1.y, c0 + 1));
        }
        __syncthreads();
        if (c < 14) { load_bchunk_async(sb, c + 2, c & 1, tid); CP_COMMIT(); }
    }

    // --- Cross-lane butterfly merge (4 lanes, disjoint code sets) -> top-6
    int* ci = (int*)(smc + SM_CAND);
    #pragma unroll
    for (int s = 0; s < 2; ++s) {
        float m[6] = {tv[s][0], tv[s][1], tv[s][2], 1.0e38f, 1.0e38f, 1.0e38f};
        #pragma unroll
        for (int off = 1; off <= 2; off <<= 1) {
            float p[6];
            #pragma unroll
            for (int j = 0; j < 6; ++j) p[j] = __shfl_xor_sync(0xffffffffu, m[j], off);
            #pragma unroll
            for (int j = 0; j < 6; ++j) ins6(m, p[j]);
        }
        if ((lane & 3) == 0) {
            int row = wid * 16 + s * 8 + (lane >> 2);
            #pragma unroll
            for (int j = 0; j < NCAND; ++j)
                ci[row * NCAND + j] = (int)(__float_as_uint(m[j]) & 1023u);
        }
    }
    __syncthreads();

    // --- Epilogue: 2 threads per row, each owns 32 dims
    const int row = tid >> 1;
    const int hh  = tid & 1;
    const float* zr = zb + row;

    float zh[32];
    #pragma unroll
    for (int k = 0; k < 32; ++k) zh[k] = zr[(size_t)(hh * 32 + k) * TT];

    // Exact fp32 rescore of 6 candidates (split over dim halves, shfl combine)
    float bestv = 3.4e38f;
    int   besti = 0;
    #pragma unroll
    for (int j = 0; j < NCAND; ++j) {
        int idx = ci[row * NCAND + j];
        const float4* er = (const float4*)(emb + (size_t)idx * DD + hh * 32);
        float dot = 0.0f;
        #pragma unroll
        for (int q = 0; q < 8; ++q) {
            float4 e4 = __ldg(er + q);
            dot = fmaf(zh[4 * q + 0], e4.x, dot);
            dot = fmaf(zh[4 * q + 1], e4.y, dot);
            dot = fmaf(zh[4 * q + 2], e4.z, dot);
            dot = fmaf(zh[4 * q + 3], e4.w, dot);
        }
        dot += __shfl_xor_sync(0xffffffffu, dot, 1);
        float v = g_hn[idx] - dot;
        if (v < bestv || (v == bestv && idx < besti)) { bestv = v; besti = idx; }
    }

    // Quantized write + loss + dw for own half
    const float4* er = (const float4*)(emb + (size_t)besti * DD + hh * 32);
    float* oq = out + OFF_Q + (size_t)b * (DD * TT) + t0 + row;
    float* dwp = g_dw + (size_t)besti * DD + hh * 32;
    float lsum = 0.0f;
    #pragma unroll
    for (int q = 0; q < 8; ++q) {
        float4 e4 = __ldg(er + q);
        int d = hh * 32 + 4 * q;
        oq[(size_t)(d + 0) * TT] = e4.x;
        oq[(size_t)(d + 1) * TT] = e4.y;
        oq[(size_t)(d + 2) * TT] = e4.z;
        oq[(size_t)(d + 3) * TT] = e4.w;
        float q0 = e4.x - zh[4 * q + 0], q1 = e4.y - zh[4 * q + 1];
        float q2 = e4.z - zh[4 * q + 2], q3 = e4.w - zh[4 * q + 3];
        lsum += q0 * q0 + q1 * q1 + q2 * q2 + q3 * q3;
        asm volatile("red.global.add.v4.f32 [%0], {%1,%2,%3,%4};"
                     :: "l"(dwp + 4 * q),
                        "f"(zh[4 * q + 0]), "f"(zh[4 * q + 1]),
                        "f"(zh[4 * q + 2]), "f"(zh[4 * q + 3]) : "memory");
    }
    if (hh == 0) {
        out[OFF_CODES + n0 + row] = (float)besti;
        atomicAdd(&g_counts[besti], 1.0f);
    }

    #pragma unroll
    for (int o = 16; o; o >>= 1) lsum += __shfl_xor_sync(0xffffffffu, lsum, o);
    if (lane == 0) swr[wid] = lsum;
    __syncthreads();
    if (tid == 0)
        atomicAdd(&g_loss, swr[0] + swr[1] + swr[2] + swr[3]);
}

// ---------------------------------------------------------------------------
// Finalize (merged): per-block nsum reduction, new_cs/loss (block 0),
// new_w + new_embedding everywhere.  256 blocks x 256 threads.
// ---------------------------------------------------------------------------
__global__ __launch_bounds__(256) void vq_fin(
        const float* __restrict__ ema_cs,
        const float* __restrict__ ema_w,
        float* __restrict__ out) {
    __shared__ float sw[8];
    __shared__ float snv;
    int tid = threadIdx.x;
    int i = blockIdx.x * 256 + tid;

    float s = 0.0f;
    #pragma unroll
    for (int j = 0; j < 4; ++j) {
        int k = tid * 4 + j;
        s += DECAYF * ema_cs[k] + OMD * g_counts[k];
    }
    #pragma unroll
    for (int o = 16; o; o >>= 1) s += __shfl_xor_sync(0xffffffffu, s, o);
    if ((tid & 31) == 0) sw[tid >> 5] = s;
    __syncthreads();
    if (tid < 32) {
        float u = (tid < 8) ? sw[tid] : 0.0f;
        #pragma unroll
        for (int o = 4; o; o >>= 1) u += __shfl_xor_sync(0xffffffffu, u, o);
        if (tid == 0) snv = u;
    }
    __syncthreads();
    float nsum = snv;

    if (blockIdx.x == 0) {
        #pragma unroll
        for (int j = 0; j < 4; ++j) {
            int k = tid * 4 + j;
            out[OFF_NEWCS + k] = DECAYF * ema_cs[k] + OMD * g_counts[k];
        }
        if (tid == 0) out[OFF_LOSS] = COMMITF * g_loss * (1.0f / (float)QE);
    }

    int k = i >> 6;
    float cs = DECAYF * ema_cs[k] + OMD * g_counts[k];
    float cluster = (cs + EPSF) / (nsum + (float)KC * EPSF) * nsum;
    float nw = DECAYF * ema_w[i] + OMD * g_dw[i];
    out[OFF_NEWW + i] = nw;
    out[OFF_NEWEMB + i] = nw * (1.0f / cluster);
}

// ---------------------------------------------------------------------------
extern "C" void kernel_launch(void* const* d_in, const int* in_sizes, int n_in,
                              void* d_out, int out_size) {
    const float* z      = (const float*)d_in[0];
    const float* emb    = (const float*)d_in[1];
    const float* ema_cs = (const float*)d_in[2];
    const float* ema_w  = (const float*)d_in[3];
    float* out = (float*)d_out;

    cudaFuncSetAttribute(vq_main_mma, cudaFuncAttributeMaxDynamicSharedMemorySize, SM_TOTAL);

    vq_prep<<<256, 256>>>(emb);
    vq_main_mma<<<1024, 128, SM_TOTAL>>>(z, emb, out);
    vq_fin<<<256, 256>>>(ema_cs, ema_w, out);
}

// round 12
// speedup vs baseline: 1.5311x; 1.0500x over previous
#include <cuda_runtime.h>
#include <cuda_fp16.h>
#include <cstdint>

// Problem constants
#define KC   1024
#define DD   64
#define BB   32
#define TT   2048
#define NV   (BB*TT)
#define QE   (BB*DD*TT)
#define DECAYF 0.99f
#define OMD    (1.0f - 0.99f)
#define COMMITF 0.25f
#define EPSF 1e-5f
#define NCAND 6
#define HBIAS 64.0f

// Output layout (flat float32, reference tuple order)
#define OFF_Q      0
#define OFF_LOSS   (OFF_Q + QE)
#define OFF_CODES  (OFF_LOSS + 1)
#define OFF_NEWEMB (OFF_CODES + NV)
#define OFF_NEWCS  (OFF_NEWEMB + KC*DD)
#define OFF_NEWW   (OFF_NEWCS + KC)

// Scratch (device globals — no allocation)
__device__ float    g_hn[KC];        // fp32 exact half-norms (rescore)
__device__ uint16_t g_hnh[KC];       // fp16 (half-norm + HBIAS) screen offsets
__device__ float    g_counts[KC];
__device__ float    g_dw[KC*DD];
__device__ float    g_loss;
__device__ __align__(256) uint16_t g_ehi[KC*DD];   // fp16 embedding

#define SWZ(o) ((o) ^ (((o) >> 3) & 0x70))

__device__ __forceinline__ uint32_t smem_u32(const void* p) {
    uint32_t a;
    asm("{ .reg .u64 t; cvta.to.shared.u64 t, %1; cvt.u32.u64 %0, t; }" : "=r"(a) : "l"(p));
    return a;
}

// fp16 MMA with fp16 accumulators: D(2 regs) = A(4) * B(2) + D
#define MMA_F16A(acc, A, B0, B1)                                               \
    asm volatile("mma.sync.aligned.m16n8k16.row.col.f16.f16.f16.f16 "          \
        "{%0,%1},{%2,%3,%4,%5},{%6,%7},{%0,%1};"                               \
        : "+r"((acc)[0]), "+r"((acc)[1])                                       \
        : "r"((A)[0]), "r"((A)[1]), "r"((A)[2]), "r"((A)[3]),                  \
          "r"(B0), "r"(B1))

#define LDSM4(r0, r1, r2, r3, a)                                               \
    asm volatile("ldmatrix.sync.aligned.m8n8.x4.shared.b16 {%0,%1,%2,%3}, [%4];" \
        : "=r"(r0), "=r"(r1), "=r"(r2), "=r"(r3) : "r"(a))

// Sortable key: [fp16 score bits (hi16) | code idx (lo16)]
#define PRMTK(d, s, i, sel)                                                    \
    asm("prmt.b32 %0, %1, %2, %3;" : "=r"(d) : "r"(s), "r"(i), "n"(sel))

#define CP_ASYNC16(dst_u32, src_ptr)                                           \
    asm volatile("cp.async.cg.shared.global [%0], [%1], 16;"                   \
                 :: "r"(dst_u32), "l"(src_ptr) : "memory")
#define CP_COMMIT() asm volatile("cp.async.commit_group;" ::: "memory")
#define CP_WAIT1()  asm volatile("cp.async.wait_group 1;" ::: "memory")
#define CP_WAIT0()  asm volatile("cp.async.wait_group 0;" ::: "memory")

// SMEM layout: A-fp16 8KB | B double buffer 2x8KB | hn-half2 2KB
#define SM_AH    0
#define SM_B     8192
#define SM_HN    24576
#define SM_CAND  SM_AH                  // reused after MMA loop (64*6 ints)
#define SM_TOTAL (SM_HN + 2048 + 128)   // 26752

// ---------------------------------------------------------------------------
// Prep: zero scratch, fp16 embedding, warp-per-code half-norms (+bias)
// ---------------------------------------------------------------------------
__global__ void vq_prep(const float* __restrict__ emb) {
    int i = blockIdx.x * 256 + threadIdx.x;   // 65536 threads
    g_dw[i] = 0.0f;
    {
        __half h = __float2half_rn(emb[i]);
        g_ehi[i] = reinterpret_cast<uint16_t&>(h);
    }
    int w = i >> 5;                            // global warp id (0..2047)
    int lane = i & 31;
    if (w < KC) {
        const float2* r = (const float2*)(emb + (size_t)w * DD);
        float2 v = r[lane];
        float s = v.x * v.x + v.y * v.y;
        #pragma unroll
        for (int o = 16; o; o >>= 1) s += __shfl_xor_sync(0xffffffffu, s, o);
        if (lane == 0) {
            float hn = 0.5f * s;
            g_hn[w] = hn;
            __half hh = __float2half_rn(hn + HBIAS);   // biased -> positive scores
            g_hnh[w] = reinterpret_cast<uint16_t&>(hh);
            g_counts[w] = 0.0f;
        }
    }
    if (i == 0) g_loss = 0.0f;
}

// ---------------------------------------------------------------------------
// Main: fp16-acc HMMA screen, PRMT int keys, lane top-2, top-6 exact rescore
// ---------------------------------------------------------------------------
extern __shared__ __align__(1024) char smc[];

// Insert 2 keys into sorted ascending top-2 (v0<=v1). 6 IMNMX.
__device__ __forceinline__ void ins2p(uint32_t v[2], uint32_t a, uint32_t b) {
    uint32_t a0 = min(a, b), a1 = max(a, b);
    uint32_t x = min(v[0], a0);
    uint32_t y = max(v[0], a0);
    uint32_t z = min(v[1], a1);
    v[0] = x;
    v[1] = min(y, z);
}
__device__ __forceinline__ void ins6u(uint32_t v[6], uint32_t t) {
    #pragma unroll
    for (int i = 0; i < 6; ++i) {
        uint32_t lo = min(t, v[i]);
        t = max(t, v[i]);
        v[i] = lo;
    }
}

// Load one 64-code B chunk (8KB) into buf
__device__ __forceinline__ void load_bchunk_async(uint32_t sb, int c, int buf, int tid) {
    #pragma unroll
    for (int i = 0; i < 4; ++i) {
        int idx  = tid + i * 128;            // 0..511
        int code = idx >> 3;                 // 0..63
        int ch   = idx & 7;
        const uint16_t* src = g_ehi + (size_t)(c * 64 + code) * DD + ch * 8;
        uint32_t doff = SM_B + buf * 8192 + code * 128 + ((ch ^ (code & 7)) * 16);
        CP_ASYNC16(sb + doff, src);
    }
}

__global__ __launch_bounds__(128, 8) void vq_main_mma(
        const float* __restrict__ z,
        const float* __restrict__ emb,
        float* __restrict__ out) {
    __shared__ float swr[4];
    const int tid  = threadIdx.x;
    const int wid  = tid >> 5;
    const int lane = tid & 31;
    const uint32_t sb = smem_u32(smc);

    const int n0 = blockIdx.x * 64;          // first vector of this CTA
    const int b  = n0 >> 11;
    const int t0 = n0 & 2047;
    const float* zb = z + (size_t)b * (DD * TT) + t0;

    // --- Stage A: 2 threads per row, each 32 dims; NEGATED fp16, swizzled
    {
        int r  = tid & 63;
        int hf = tid >> 6;                   // dim half
        const float* zr = zb + r;
        #pragma unroll
        for (int j = 0; j < 16; ++j) {
            int d = hf * 32 + 2 * j;
            __half h0 = __float2half_rn(-zr[(size_t)d * TT]);
            __half h1 = __float2half_rn(-zr[(size_t)(d + 1) * TT]);
            uint32_t hp = (uint32_t)reinterpret_cast<uint16_t&>(h0)
                        | ((uint32_t)reinterpret_cast<uint16_t&>(h1) << 16);
            *(uint32_t*)(smc + SM_AH + SWZ((uint32_t)(r * 128 + 2 * d))) = hp;
        }
    }
    // biased hn table as half2 words
    uint32_t* shn2 = (uint32_t*)(smc + SM_HN);
    #pragma unroll
    for (int i = 0; i < 4; ++i)
        shn2[tid + i * 128] = ((const uint32_t*)g_hnh)[tid + i * 128];

    // Prefetch B chunks 0, 1
    load_bchunk_async(sb, 0, 0, tid); CP_COMMIT();
    load_bchunk_async(sb, 1, 1, tid); CP_COMMIT();

    __syncthreads();

    // ldmatrix lane constants
    const uint32_t r7 = (uint32_t)(lane & 7);
    const uint32_t mm = (uint32_t)(lane >> 3);

    // --- A fragments via 4x ldmatrix.x4: 1 m-tile/warp, 4 k-steps x 4 regs
    uint32_t ah[4][4];
    {
        uint32_t arow = (uint32_t)(wid * 16) + (mm & 1) * 8 + r7;
        uint32_t acol = (mm >> 1) * 16;
        #pragma unroll
        for (int s = 0; s < 4; ++s) {
            uint32_t addr = sb + SM_AH + arow * 128
                          + (((uint32_t)(s * 32) + acol) ^ (r7 * 16));
            LDSM4(ah[s][0], ah[s][1], ah[s][2], ah[s][3], addr);
        }
    }

    // B ldmatrix per-lane constant offset within a chunk buffer
    const uint32_t blconst = r7 * 128 + ((mm * 16) ^ (r7 * 16));

    // Running index register: lo16 = even code, hi16 = odd code
    const uint32_t q2 = (uint32_t)((lane & 3) * 2);
    uint32_t ie = q2 | ((q2 + 1) << 16);

    // Per-slot sorted top-2 key trackers
    uint32_t tv[2][2] = {{0xFFFFFFFFu, 0xFFFFFFFFu}, {0xFFFFFFFFu, 0xFFFFFFFFu}};

    // --- Chunk loop: 16 chunks x 64 codes
    #pragma unroll 1
    for (int c = 0; c < 16; ++c) {
        if (c < 15) CP_WAIT1(); else CP_WAIT0();
        __syncthreads();
        const uint32_t bbase = sb + SM_B + (uint32_t)((c & 1) * 8192) + blconst;

        #pragma unroll 1
        for (int nt = 0; nt < 8; ++nt) {
            uint32_t a1 = bbase + (uint32_t)(nt * 1024);
            uint32_t a2 = a1 ^ 64u;
            uint32_t bh[4][2];
            LDSM4(bh[0][0], bh[0][1], bh[1][0], bh[1][1], a1);  // k-halves 0-3
            LDSM4(bh[2][0], bh[2][1], bh[3][0], bh[3][1], a2);  // k-halves 4-7

            uint32_t h01 = shn2[c * 32 + nt * 4 + (lane & 3)];
            // single 4-deep chain per row; biased h seeds the accumulator
            uint32_t aA[2] = {h01, h01};
            MMA_F16A(aA, ah[0], bh[0][0], bh[0][1]);
            MMA_F16A(aA, ah[1], bh[1][0], bh[1][1]);
            MMA_F16A(aA, ah[2], bh[2][0], bh[2][1]);
            MMA_F16A(aA, ah[3], bh[3][0], bh[3][1]);

            // sortable keys: [score fp16 | idx16]
            uint32_t k0e, k0o, k1e, k1o;
            PRMTK(k0e, aA[0], ie, 0x1054);
            PRMTK(k0o, aA[0], ie, 0x3276);
            PRMTK(k1e, aA[1], ie, 0x1054);
            PRMTK(k1o, aA[1], ie, 0x3276);
            ins2p(tv[0], k0e, k0o);
            ins2p(tv[1], k1e, k1o);
            ie += 0x00080008u;
        }
        __syncthreads();
        if (c < 14) { load_bchunk_async(sb, c + 2, c & 1, tid); CP_COMMIT(); }
    }

    // --- Cross-lane butterfly merge (4 lanes, disjoint code sets) -> top-6
    int* ci = (int*)(smc + SM_CAND);
    #pragma unroll
    for (int s = 0; s < 2; ++s) {
        uint32_t m[6] = {tv[s][0], tv[s][1],
                         0xFFFFFFFFu, 0xFFFFFFFFu, 0xFFFFFFFFu, 0xFFFFFFFFu};
        #pragma unroll
        for (int off = 1; off <= 2; off <<= 1) {
            uint32_t p[6];
            #pragma unroll
            for (int j = 0; j < 6; ++j) p[j] = __shfl_xor_sync(0xffffffffu, m[j], off);
            #pragma unroll
            for (int j = 0; j < 6; ++j) ins6u(m, p[j]);
        }
        if ((lane & 3) == 0) {
            int row = wid * 16 + s * 8 + (lane >> 2);
            #pragma unroll
            for (int j = 0; j < NCAND; ++j)
                ci[row * NCAND + j] = (int)(m[j] & 0xFFFFu);
        }
    }
    __syncthreads();

    // --- Epilogue: 2 threads per row, each owns 32 dims
    const int row = tid >> 1;
    const int hh  = tid & 1;
    const float* zr = zb + row;

    float zh[32];
    #pragma unroll
    for (int k = 0; k < 32; ++k) zh[k] = zr[(size_t)(hh * 32 + k) * TT];

    // Exact fp32 rescore of 6 candidates (split over dim halves, shfl combine)
    float bestv = 3.4e38f;
    int   besti = 0;
    #pragma unroll
    for (int j = 0; j < NCAND; ++j) {
        int idx = ci[row * NCAND + j];
        const float4* er = (const float4*)(emb + (size_t)idx * DD + hh * 32);
        float dot = 0.0f;
        #pragma unroll
        for (int q = 0; q < 8; ++q) {
            float4 e4 = __ldg(er + q);
            dot = fmaf(zh[4 * q + 0], e4.x, dot);
            dot = fmaf(zh[4 * q + 1], e4.y, dot);
            dot = fmaf(zh[4 * q + 2], e4.z, dot);
            dot = fmaf(zh[4 * q + 3], e4.w, dot);
        }
        dot += __shfl_xor_sync(0xffffffffu, dot, 1);
        float v = g_hn[idx] - dot;
        if (v < bestv || (v == bestv && idx < besti)) { bestv = v; besti = idx; }
    }

    // Quantized write + loss + dw for own half
    const float4* er = (const float4*)(emb + (size_t)besti * DD + hh * 32);
    float* oq = out + OFF_Q + (size_t)b * (DD * TT) + t0 + row;
    float* dwp = g_dw + (size_t)besti * DD + hh * 32;
    float lsum = 0.0f;
    #pragma unroll
    for (int q = 0; q < 8; ++q) {
        float4 e4 = __ldg(er + q);
        int d = hh * 32 + 4 * q;
        oq[(size_t)(d + 0) * TT] = e4.x;
        oq[(size_t)(d + 1) * TT] = e4.y;
        oq[(size_t)(d + 2) * TT] = e4.z;
        oq[(size_t)(d + 3) * TT] = e4.w;
        float q0 = e4.x - zh[4 * q + 0], q1 = e4.y - zh[4 * q + 1];
        float q2v = e4.z - zh[4 * q + 2], q3 = e4.w - zh[4 * q + 3];
        lsum += q0 * q0 + q1 * q1 + q2v * q2v + q3 * q3;
        asm volatile("red.global.add.v4.f32 [%0], {%1,%2,%3,%4};"
                     :: "l"(dwp + 4 * q),
                        "f"(zh[4 * q + 0]), "f"(zh[4 * q + 1]),
                        "f"(zh[4 * q + 2]), "f"(zh[4 * q + 3]) : "memory");
    }
    if (hh == 0) {
        out[OFF_CODES + n0 + row] = (float)besti;
        atomicAdd(&g_counts[besti], 1.0f);
    }

    #pragma unroll
    for (int o = 16; o; o >>= 1) lsum += __shfl_xor_sync(0xffffffffu, lsum, o);
    if (lane == 0) swr[wid] = lsum;
    __syncthreads();
    if (tid == 0)
        atomicAdd(&g_loss, swr[0] + swr[1] + swr[2] + swr[3]);
}

// ---------------------------------------------------------------------------
// Finalize (merged): per-block nsum reduction, new_cs/loss (block 0),
// new_w + new_embedding everywhere.  256 blocks x 256 threads.
// ---------------------------------------------------------------------------
__global__ __launch_bounds__(256) void vq_fin(
        const float* __restrict__ ema_cs,
        const float* __restrict__ ema_w,
        float* __restrict__ out) {
    __shared__ float sw[8];
    __shared__ float snv;
    int tid = threadIdx.x;
    int i = blockIdx.x * 256 + tid;

    float s = 0.0f;
    #pragma unroll
    for (int j = 0; j < 4; ++j) {
        int k = tid * 4 + j;
        s += DECAYF * ema_cs[k] + OMD * g_counts[k];
    }
    #pragma unroll
    for (int o = 16; o; o >>= 1) s += __shfl_xor_sync(0xffffffffu, s, o);
    if ((tid & 31) == 0) sw[tid >> 5] = s;
    __syncthreads();
    if (tid < 32) {
        float u = (tid < 8) ? sw[tid] : 0.0f;
        #pragma unroll
        for (int o = 4; o; o >>= 1) u += __shfl_xor_sync(0xffffffffu, u, o);
        if (tid == 0) snv = u;
    }
    __syncthreads();
    float nsum = snv;

    if (blockIdx.x == 0) {
        #pragma unroll
        for (int j = 0; j < 4; ++j) {
            int k = tid * 4 + j;
            out[OFF_NEWCS + k] = DECAYF * ema_cs[k] + OMD * g_counts[k];
        }
        if (tid == 0) out[OFF_LOSS] = COMMITF * g_loss * (1.0f / (float)QE);
    }

    int k = i >> 6;
    float cs = DECAYF * ema_cs[k] + OMD * g_counts[k];
    float cluster = (cs + EPSF) / (nsum + (float)KC * EPSF) * nsum;
    float nw = DECAYF * ema_w[i] + OMD * g_dw[i];
    out[OFF_NEWW + i] = nw;
    out[OFF_NEWEMB + i] = nw * (1.0f / cluster);
}

// ---------------------------------------------------------------------------
extern "C" void kernel_launch(void* const* d_in, const int* in_sizes, int n_in,
                              void* d_out, int out_size) {
    const float* z      = (const float*)d_in[0];
    const float* emb    = (const float*)d_in[1];
    const float* ema_cs = (const float*)d_in[2];
    const float* ema_w  = (const float*)d_in[3];
    float* out = (float*)d_out;

    cudaFuncSetAttribute(vq_main_mma, cudaFuncAttributeMaxDynamicSharedMemorySize, SM_TOTAL);

    vq_prep<<<256, 256>>>(emb);
    vq_main_mma<<<1024, 128, SM_TOTAL>>>(z, emb, out);
    vq_fin<<<256, 256>>>(ema_cs, ema_w, out);
}